// round 11
// baseline (speedup 1.0000x reference)
#include <cuda_runtime.h>

// MPM p2g scatter: 1M particles -> 128^3 grid of (mass, mom.x, mom.y, mom.z)
// R10: scatter into a 2x2x2-BLOCKED scratch layout so one 128B line holds a
// 2x2x2 supercell: a particle's 8 corners touch E[(3/2)^3]=3.375 lines vs
// 4.5 in the linear layout (the measured binder is L1tex line-replay at
// ~2.07 cyc/line). Pipeline: zero(scratch) -> [PDL] corner-parallel v4-REDG
// scatter into scratch -> remap blocked->linear into out (overwrites every
// cell, so out itself never needs zeroing).

static constexpr float INV_CELL = 64.0f;
static constexpr int NUM_CELLS = 128 * 128 * 128;

// Blocked scratch: 33.5MB device global, 128B-aligned (block == cache line).
__device__ __align__(128) float4 g_scratch[NUM_CELLS];

__device__ __forceinline__ void red_add_v4(float* p, float a, float b, float c, float d) {
    asm volatile("red.global.add.v4.f32 [%0], {%1, %2, %3, %4};"
                 :: "l"(p), "f"(a), "f"(b), "f"(c), "f"(d)
                 : "memory");
}

// ---------- K1: zero the blocked scratch ----------
__global__ __launch_bounds__(256) void zero_scratch_kernel() {
    // Trigger at top: dependent scatter grid may begin its front end now;
    // its REDGs still gate on full completion via cudaGridDependencySynchronize.
    cudaTriggerProgrammaticLaunchCompletion();
    int stride = gridDim.x * blockDim.x;
    for (int i = blockIdx.x * blockDim.x + threadIdx.x; i < NUM_CELLS; i += stride)
        g_scratch[i] = make_float4(0.f, 0.f, 0.f, 0.f);
}

// ---------- K2: corner-parallel scatter into blocked scratch ----------
static constexpr int WARP_STAGE = 224; // pos[96] | vel[96] | mass[32] floats

__global__ __launch_bounds__(256) void p2g_corner_kernel(
    const float* __restrict__ pos,
    const float* __restrict__ vel,
    const float* __restrict__ mass,
    int n)
{
    __shared__ float stage[8 * WARP_STAGE];

    int warp_id = (blockIdx.x * blockDim.x + threadIdx.x) >> 5;
    int lane = threadIdx.x & 31;
    int wib = threadIdx.x >> 5;
    float* sp = stage + wib * WARP_STAGE;

    int base = warp_id * 32;
    if (base >= n) {
        cudaGridDependencySynchronize();
        return;
    }

    // front end (overlaps the zero kernel under PDL)
    if (base + 32 <= n) {
        const float4* pos4 = (const float4*)pos;
        const float4* vel4 = (const float4*)vel;
        const float4* mass4 = (const float4*)mass;
        if (lane < 24) {
            ((float4*)sp)[lane]        = pos4[warp_id * 24 + lane];
            ((float4*)(sp + 96))[lane] = vel4[warp_id * 24 + lane];
        } else {
            ((float4*)(sp + 192))[lane - 24] = mass4[warp_id * 8 + (lane - 24)];
        }
    } else {
        int nv = n - base;
        for (int e = lane; e < nv * 3; e += 32) {
            sp[e]      = pos[base * 3 + e];
            sp[96 + e] = vel[base * 3 + e];
        }
        if (lane < nv) sp[192 + lane] = mass[base + lane];
    }
    __syncwarp();

    int p_local = lane >> 3;
    int c = lane & 7;                 // bit0=z, bit1=x, bit2=y
    int cz = c & 1, cx = (c >> 1) & 1, cy = (c >> 2) & 1;

    cudaGridDependencySynchronize();  // scratch fully zeroed

    float* scr = (float*)g_scratch;

#pragma unroll
    for (int s = 0; s < 8; s++) {
        int idx = s * 4 + p_local;
        if (base + idx < n) {
            float px = sp[3 * idx + 0];
            float py = sp[3 * idx + 1];
            float pz = sp[3 * idx + 2];
            float vx = sp[96 + 3 * idx + 0];
            float vy = sp[96 + 3 * idx + 1];
            float vz = sp[96 + 3 * idx + 2];
            float m  = sp[192 + idx];

            float rx = px * INV_CELL;
            float ry = py * INV_CELL;
            float rz = pz * INV_CELL;
            float bx = floorf(rx), by = floorf(ry), bz = floorf(rz);
            float fx = rx - bx, fy = ry - by, fz = rz - bz;

            float wxv = cx ? fx : 1.f - fx;
            float wyv = cy ? fy : 1.f - fy;
            float wzv = cz ? fz : 1.f - fz;

            int X = (int)bx + cx, Y = (int)by + cy, Z = (int)bz + cz;
            // blocked address: block = (Z>>1) + (X>>1)<<6 + (Y>>1)<<12,
            //                  off   = (X&1)<<2 | (Y&1)<<1 | (Z&1)
            int blk = (Z >> 1) + ((X >> 1) << 6) + ((Y >> 1) << 12);
            int off = ((X & 1) << 2) + ((Y & 1) << 1) + (Z & 1);
            int f = (blk << 3) + off;

            float sm = wxv * wyv * wzv * m;
            red_add_v4(scr + 4 * f, sm, sm * vx, sm * vy, sm * vz);
        }
    }
}

// ---------- K3: remap blocked scratch -> linear out ----------
__global__ __launch_bounds__(256) void remap_kernel(float4* __restrict__ out) {
    int stride = gridDim.x * blockDim.x;
    for (int f = blockIdx.x * blockDim.x + threadIdx.x; f < NUM_CELLS; f += stride) {
        float4 v = g_scratch[f];      // coalesced linear read of scratch
        int b = f >> 3, off = f & 7;
        int ZB = b & 63, XB = (b >> 6) & 63, YB = (b >> 12) & 63;
        int x = (XB << 1) + ((off >> 2) & 1);
        int y = (YB << 1) + ((off >> 1) & 1);
        int z = (ZB << 1) + (off & 1);
        out[z + (x << 7) + (y << 14)] = v;  // ~4 lines/warp-instr write
    }
}

extern "C" void kernel_launch(void* const* d_in, const int* in_sizes, int n_in,
                              void* d_out, int out_size) {
    const float* pos  = (const float*)d_in[0];
    const float* vel  = (const float*)d_in[1];
    const float* mass = (const float*)d_in[2];
    float4* out4 = (float4*)d_out;

    // K1: zero scratch (triggers PDL completion at its start).
    zero_scratch_kernel<<<2048, 256>>>();

    // K2: scatter, programmatically dependent on K1.
    int n = in_sizes[2];
    int warps = (n + 31) / 32;
    int blocks = (warps + 7) / 8;

    cudaLaunchConfig_t cfg = {};
    cfg.gridDim = dim3(blocks, 1, 1);
    cfg.blockDim = dim3(256, 1, 1);
    cfg.dynamicSmemBytes = 0;
    cfg.stream = 0;
    cudaLaunchAttribute attr[1];
    attr[0].id = cudaLaunchAttributeProgrammaticStreamSerialization;
    attr[0].val.programmaticStreamSerializationAllowed = 1;
    cfg.attrs = attr;
    cfg.numAttrs = 1;
    cudaLaunchKernelEx(&cfg, p2g_corner_kernel, pos, vel, mass, n);

    // K3: blocked -> linear remap (full stream serialization after K2).
    remap_kernel<<<2048, 256>>>(out4);
}